// round 16
// baseline (speedup 1.0000x reference)
#include <cuda_runtime.h>
#include <cuda_fp16.h>
#include <cstdint>
#include <math.h>

// ---------------- problem constants ----------------
#define BATCH 4
#define SEQ   4096
#define CH    768
#define NHEAD 12
#define HDIM  64
#define M_ROWS (BATCH * SEQ)          // 16384
#define QKV_N  (3 * CH)               // 2304
#define BNC   (M_ROWS * CH)
#define SCALE 0.125f
#define EPSV  1e-10f
#define KDIM  768
#define ASCALE 4096.0f
#define INV_ASCALE (1.0f / 4096.0f)
#define KV_CTAS 1536                  // 12 * 128
#define NMT 128                       // number of m tiles

// ---------------- scratch (device globals) ----------------
__device__ __half g_x16[M_ROWS * CH];
__device__ __half g_wq[QKV_N * CH];
__device__ __half g_w1[CH * CH], g_w2[CH * CH];
__device__ __half g_aL[M_ROWS * CH];
__device__ __half g_aG[M_ROWS * CH];
__device__ float g_red[3 * BATCH * CH];       // [kv | lkv | ksum]
__device__ int   g_cnt[1 + NMT];              // [0]=kv count, [1+mt]=q count

// ---------------- helpers ----------------
__device__ __forceinline__ float delu_f(float x) {
    return (x >= 0.0f) ? fmaf(10.0f, x, 1.0f) : __expf(10.0f * x);
}

__device__ __forceinline__ uint32_t smem_u32(const void* p) {
    uint32_t a;
    asm("{ .reg .u64 t; cvta.to.shared.u64 t, %1; cvt.u32.u64 %0, t; }" : "=r"(a) : "l"(p));
    return a;
}

__device__ __forceinline__ void cp16(uint32_t s, const void* g) {
    asm volatile("cp.async.cg.shared.global [%0], [%1], 16;" :: "r"(s), "l"(g));
}
#define CP_COMMIT() asm volatile("cp.async.commit_group;" ::: "memory")

__device__ __forceinline__ void ldsm4(uint32_t* r, uint32_t a) {
    asm volatile("ldmatrix.sync.aligned.m8n8.x4.shared.b16 {%0,%1,%2,%3}, [%4];"
                 : "=r"(r[0]), "=r"(r[1]), "=r"(r[2]), "=r"(r[3]) : "r"(a));
}

__device__ __forceinline__ void mma16816(float* c, const uint32_t* a, const uint32_t* b) {
    asm volatile(
        "mma.sync.aligned.m16n8k16.row.col.f32.f16.f16.f32 "
        "{%0,%1,%2,%3},{%4,%5,%6,%7},{%8,%9},{%0,%1,%2,%3};"
        : "+f"(c[0]), "+f"(c[1]), "+f"(c[2]), "+f"(c[3])
        : "r"(a[0]), "r"(a[1]), "r"(a[2]), "r"(a[3]), "r"(b[0]), "r"(b[1]));
}

// ---------------- tiling: CTA 128x128, warp 64x32, BK=64 ----------------
#define BMt 128
#define BNt 128
#define BKt 64
#define NKT (KDIM / BKt)             // 12
#define TILE_B 16384
#define OFF_B TILE_B
#define STG (2 * TILE_B)             // 32 KB per stage
#define NSTG 3
#define GEMM_SMEM (NSTG * STG + 1024)

// Swizzle hoist (corrected): rowbase bits 5,6 are zero, so
// (rowbase + kofs) ^ swz(rowbase) == ((rowbase ^ swz) ^ kofs). kofs must be
// combined with XOR (it collides with the XOR-modified bits 4-6); mf*2048 is
// bits >=11, plain add is safe.
#define GEMM_MAINLOOP(LOADFN)                                                 \
    LOADFN(0, 0);                                                             \
    LOADFN(1, 1);                                                             \
    const uint32_t arow = (uint32_t)((warp_m * 64 + (lane & 15)) * 128 + (lane >> 4) * 16); \
    const uint32_t brow = (uint32_t)((warp_n * 32 + (lane & 15)) * 128 + (lane >> 4) * 16); \
    const uint32_t aswz = arow ^ ((arow >> 3) & 0x70);                        \
    const uint32_t bswz = (brow ^ ((brow >> 3) & 0x70)) + OFF_B;              \
    for (int c = 0; c < NKT; c++) {                                           \
        const int s = c % NSTG;                                               \
        if (c == NKT - 1) asm volatile("cp.async.wait_group 0;" ::: "memory");\
        else              asm volatile("cp.async.wait_group 1;" ::: "memory");\
        __syncthreads();                                                      \
        if (c + 2 < NKT) LOADFN(c + 2, (c + 2) % NSTG);                       \
        const uint32_t abase = sbase + s * STG + aswz;                        \
        const uint32_t bbase = sbase + s * STG + bswz;                        \
        _Pragma("unroll")                                                     \
        for (int ks = 0; ks < 4; ks++) {                                      \
            const uint32_t kofs = ks * 32;                                    \
            uint32_t ah[4][4], bh[4][2];                                      \
            _Pragma("unroll")                                                 \
            for (int mf = 0; mf < 4; mf++)                                    \
                ldsm4(ah[mf], (abase + mf * 2048) ^ kofs);                    \
            _Pragma("unroll")                                                 \
            for (int gg = 0; gg < 2; gg++) {                                  \
                uint32_t qq[4];                                               \
                ldsm4(qq, (bbase + gg * 2048) ^ kofs);                        \
                bh[gg * 2][0] = qq[0]; bh[gg * 2][1] = qq[2];                 \
                bh[gg * 2 + 1][0] = qq[1]; bh[gg * 2 + 1][1] = qq[3];         \
            }                                                                 \
            _Pragma("unroll")                                                 \
            for (int mf = 0; mf < 4; mf++)                                    \
                _Pragma("unroll")                                             \
                for (int nf = 0; nf < 4; nf++)                                \
                    mma16816(acc[mf][nf], ah[mf], bh[nf]);                    \
        }                                                                     \
    }

// ======== mega-kernel: z<12 kv+red | z in [12,18) q+attn | z>=18 proj ======
__global__ void __launch_bounds__(256, 2)
gemm_fused(const __half* __restrict__ A, const __half* __restrict__ Wq,
           const float* __restrict__ y, float* __restrict__ red,
           int* __restrict__ cnt,
           __half* __restrict__ oL, __half* __restrict__ oG,
           const __half* __restrict__ w1, const __half* __restrict__ w2,
           const float* __restrict__ b1, const float* __restrict__ b2,
           float* __restrict__ out)
{
    extern __shared__ char smraw[];
    const uint32_t sbase = (smem_u32(smraw) + 1023u) & ~1023u;
    const int tid = threadIdx.x;
    const int lane = tid & 31, wid = tid >> 5;
    const int warp_m = wid >> 2, warp_n = wid & 3;
    const int mt = blockIdx.x;
    const int m0 = mt * BMt;
    const int b = m0 >> 12;
    const int z = blockIdx.z;

    float acc[4][4][4];
#pragma unroll
    for (int i = 0; i < 4; i++)
#pragma unroll
        for (int j = 0; j < 4; j++)
#pragma unroll
            for (int e = 0; e < 4; e++) acc[i][j][e] = 0.0f;

    if (z < 12) {
        // ================= kv + diagonal reductions =================
        const int g64 = z * 64;
        auto load_tile = [&](int kt, int s) {
            const uint32_t st = sbase + s * STG;
            const int kb = kt * BKt;
#pragma unroll
            for (int i = tid; i < 1024; i += 256) {
                const int r = i >> 3, cc = i & 7;
                uint32_t off = (uint32_t)(r * 128 + cc * 16);
                off ^= (off >> 3) & 0x70;
                cp16(st + off, A + (size_t)(m0 + r) * KDIM + kb + cc * 8);
                const int rg = (r < 64) ? (CH + g64 + r) : (2 * CH + g64 + r - 64);
                cp16(st + OFF_B + off, Wq + (size_t)rg * KDIM + kb + cc * 8);
            }
            CP_COMMIT();
        };

        GEMM_MAINLOOP(load_tile)

        __syncthreads();
        float* vbuf = reinterpret_cast<float*>(smraw); // [128][65]
        const bool is_v = (warp_n >= 2);

        if (is_v) {
#pragma unroll
            for (int mf = 0; mf < 4; mf++) {
                const int r = warp_m * 64 + mf * 16 + (lane >> 2);
#pragma unroll
                for (int nf = 0; nf < 4; nf++) {
                    const int cl = (warp_n - 2) * 32 + nf * 8 + (lane & 3) * 2;
                    vbuf[r * 65 + cl]           = acc[mf][nf][0];
                    vbuf[r * 65 + cl + 1]       = acc[mf][nf][1];
                    vbuf[(r + 8) * 65 + cl]     = acc[mf][nf][2];
                    vbuf[(r + 8) * 65 + cl + 1] = acc[mf][nf][3];
                }
            }
        }
        __syncthreads();

        if (is_v) {
            float s0[4], s1[4];
#pragma unroll
            for (int nf = 0; nf < 4; nf++) { s0[nf] = 0.f; s1[nf] = 0.f; }
#pragma unroll
            for (int mf = 0; mf < 4; mf++) {
                const int r = m0 + warp_m * 64 + mf * 16 + (lane >> 2);
#pragma unroll
                for (int nf = 0; nf < 4; nf++) {
                    const int cg = g64 + (warp_n - 2) * 32 + nf * 8 + (lane & 3) * 2;
                    const float2 ya = *reinterpret_cast<const float2*>(y + (size_t)r * CH + cg);
                    const float2 yb = *reinterpret_cast<const float2*>(y + (size_t)(r + 8) * CH + cg);
                    s0[nf] = fmaf(delu_f(ya.x), acc[mf][nf][0], s0[nf]);
                    s1[nf] = fmaf(delu_f(ya.y), acc[mf][nf][1], s1[nf]);
                    s0[nf] = fmaf(delu_f(yb.x), acc[mf][nf][2], s0[nf]);
                    s1[nf] = fmaf(delu_f(yb.y), acc[mf][nf][3], s1[nf]);
                }
            }
#pragma unroll
            for (int nf = 0; nf < 4; nf++) {
#pragma unroll
                for (int off = 4; off <= 16; off <<= 1) {
                    s0[nf] += __shfl_xor_sync(0xffffffffu, s0[nf], off);
                    s1[nf] += __shfl_xor_sync(0xffffffffu, s1[nf], off);
                }
            }
            if (lane < 4) {
#pragma unroll
                for (int nf = 0; nf < 4; nf++) {
                    const int cg = g64 + (warp_n - 2) * 32 + nf * 8 + lane * 2;
                    atomicAdd(&red[BATCH * CH + b * CH + cg],     s0[nf]);
                    atomicAdd(&red[BATCH * CH + b * CH + cg + 1], s1[nf]);
                }
            }
        } else {
            float p0[4], p1[4], k0[4], k1[4];
#pragma unroll
            for (int nf = 0; nf < 4; nf++) { p0[nf] = p1[nf] = k0[nf] = k1[nf] = 0.f; }
#pragma unroll
            for (int mf = 0; mf < 4; mf++) {
                const int r = warp_m * 64 + mf * 16 + (lane >> 2);
#pragma unroll
                for (int nf = 0; nf < 4; nf++) {
                    const int cl = warp_n * 32 + nf * 8 + (lane & 3) * 2;
                    const float ka = delu_f(acc[mf][nf][0]);
                    const float kb = delu_f(acc[mf][nf][1]);
                    const float kc = delu_f(acc[mf][nf][2]);
                    const float kd = delu_f(acc[mf][nf][3]);
                    p0[nf] = fmaf(ka, vbuf[r * 65 + cl],           p0[nf]);
                    p1[nf] = fmaf(kb, vbuf[r * 65 + cl + 1],       p1[nf]);
                    p0[nf] = fmaf(kc, vbuf[(r + 8) * 65 + cl],     p0[nf]);
                    p1[nf] = fmaf(kd, vbuf[(r + 8) * 65 + cl + 1], p1[nf]);
                    k0[nf] += ka + kc;
                    k1[nf] += kb + kd;
                }
            }
#pragma unroll
            for (int nf = 0; nf < 4; nf++) {
#pragma unroll
                for (int off = 4; off <= 16; off <<= 1) {
                    p0[nf] += __shfl_xor_sync(0xffffffffu, p0[nf], off);
                    p1[nf] += __shfl_xor_sync(0xffffffffu, p1[nf], off);
                    k0[nf] += __shfl_xor_sync(0xffffffffu, k0[nf], off);
                    k1[nf] += __shfl_xor_sync(0xffffffffu, k1[nf], off);
                }
            }
            if (lane < 4) {
#pragma unroll
                for (int nf = 0; nf < 4; nf++) {
                    const int cg = g64 + warp_n * 32 + nf * 8 + lane * 2;
                    atomicAdd(&red[b * CH + cg],     p0[nf]);
                    atomicAdd(&red[b * CH + cg + 1], p1[nf]);
                    atomicAdd(&red[2 * BATCH * CH + b * CH + cg],     k0[nf]);
                    atomicAdd(&red[2 * BATCH * CH + b * CH + cg + 1], k1[nf]);
                }
            }
        }
        __syncthreads();
        if (tid == 0) {
            __threadfence();
            atomicAdd(&cnt[0], 1);
        }
    } else if (z < 18) {
        // ================= q GEMM + norm + attention =================
        const int n0 = (z - 12) * BNt;
        auto load_tile = [&](int kt, int s) {
            const uint32_t st = sbase + s * STG;
            const int kb = kt * BKt;
#pragma unroll
            for (int i = tid; i < 1024; i += 256) {
                const int r = i >> 3, cc = i & 7;
                uint32_t off = (uint32_t)(r * 128 + cc * 16);
                off ^= (off >> 3) & 0x70;
                cp16(st + off,         A + (size_t)(m0 + r) * KDIM + kb + cc * 8);
                cp16(st + OFF_B + off, Wq + (size_t)(n0 + r) * KDIM + kb + cc * 8);
            }
            CP_COMMIT();
        };

        GEMM_MAINLOOP(load_tile)

        // acquire: all kv CTAs done
        if (tid == 0) {
            while (*reinterpret_cast<volatile int*>(&cnt[0]) < KV_CTAS) { }
            __threadfence();
        }
        __syncthreads();

        const float* ksb  = red + 2 * BATCH * CH + b * CH;
        const float* kvb  = red + b * CH;
        const float* lkvb = red + BATCH * CH + b * CH;

        float ks0[4], ks1[4], kv0[4], kv1[4], lk0[4], lk1[4];
#pragma unroll
        for (int nf = 0; nf < 4; nf++) {
            const int col = n0 + warp_n * 32 + nf * 8 + (lane & 3) * 2;
            ks0[nf] = ksb[col] + EPSV;       ks1[nf] = ksb[col + 1] + EPSV;
            kv0[nf] = kvb[col] * SCALE;      kv1[nf] = kvb[col + 1] * SCALE;
            lk0[nf] = lkvb[col] * SCALE;     lk1[nf] = lkvb[col + 1] * SCALE;
        }

#pragma unroll
        for (int mf = 0; mf < 4; mf++)
#pragma unroll
            for (int nf = 0; nf < 4; nf++)
#pragma unroll
                for (int e = 0; e < 4; e++) acc[mf][nf][e] = delu_f(acc[mf][nf][e]);

        float (*psum)[128] = reinterpret_cast<float (*)[128]>(smraw); // [4][128]

#pragma unroll
        for (int mf = 0; mf < 4; mf++) {
            float pa = 0.f, pb = 0.f;
#pragma unroll
            for (int nf = 0; nf < 4; nf++) {
                pa += acc[mf][nf][0] * ks0[nf] + acc[mf][nf][1] * ks1[nf];
                pb += acc[mf][nf][2] * ks0[nf] + acc[mf][nf][3] * ks1[nf];
            }
            pa += __shfl_xor_sync(0xffffffffu, pa, 1);
            pa += __shfl_xor_sync(0xffffffffu, pa, 2);
            pb += __shfl_xor_sync(0xffffffffu, pb, 1);
            pb += __shfl_xor_sync(0xffffffffu, pb, 2);
            if ((lane & 3) == 0) {
                const int rl = warp_m * 64 + mf * 16 + (lane >> 2);
                psum[warp_n][rl]     = pa;
                psum[warp_n][rl + 8] = pb;
            }
        }
        __syncthreads();

        const int hw = warp_n & ~1;
#pragma unroll
        for (int mf = 0; mf < 4; mf++) {
            const int rl = warp_m * 64 + mf * 16 + (lane >> 2);
            const float na = ASCALE / (psum[hw][rl]     + psum[hw + 1][rl]);
            const float nb = ASCALE / (psum[hw][rl + 8] + psum[hw + 1][rl + 8]);
            const int row = m0 + rl;
#pragma unroll
            for (int nf = 0; nf < 4; nf++) {
                const int col = n0 + warp_n * 32 + nf * 8 + (lane & 3) * 2;
                const size_t i0 = (size_t)row * CH + col;
                const size_t i1 = (size_t)(row + 8) * CH + col;
                *reinterpret_cast<__half2*>(oL + i0) = __halves2half2(
                    __float2half(acc[mf][nf][0] * kv0[nf] * na),
                    __float2half(acc[mf][nf][1] * kv1[nf] * na));
                *reinterpret_cast<__half2*>(oL + i1) = __halves2half2(
                    __float2half(acc[mf][nf][2] * kv0[nf] * nb),
                    __float2half(acc[mf][nf][3] * kv1[nf] * nb));
                *reinterpret_cast<__half2*>(oG + i0) = __halves2half2(
                    __float2half(acc[mf][nf][0] * lk0[nf] * na),
                    __float2half(acc[mf][nf][1] * lk1[nf] * na));
                *reinterpret_cast<__half2*>(oG + i1) = __halves2half2(
                    __float2half(acc[mf][nf][2] * lk0[nf] * nb),
                    __float2half(acc[mf][nf][3] * lk1[nf] * nb));
            }
        }
        // release this m-tile for projections
        __syncthreads();
        if (tid == 0) {
            __threadfence();
            atomicAdd(&cnt[1 + mt], 1);
        }
    } else {
        // ================= projections (z = 18..29) =================
        const int zz = z - 18;
        const int p  = zz / 6;                 // 0 -> proj1, 1 -> proj2
        const int n0 = (zz % 6) * BNt;
        const __half* Ap = p ? oG : oL;
        const __half* Bp = p ? w2 : w1;
        const float* bp  = p ? b2 : b1;
        float* Cp        = out + (size_t)p * BNC;

        // acquire: all 6 q CTAs for this m-tile finished
        if (tid == 0) {
            while (*reinterpret_cast<volatile int*>(&cnt[1 + mt]) < 6) { }
            __threadfence();
        }
        __syncthreads();

        auto load_tile = [&](int kt, int s) {
            const uint32_t st = sbase + s * STG;
            const int kb = kt * BKt;
#pragma unroll
            for (int i = tid; i < 1024; i += 256) {
                const int r = i >> 3, cc = i & 7;
                uint32_t off = (uint32_t)(r * 128 + cc * 16);
                off ^= (off >> 3) & 0x70;
                cp16(st + off,         Ap + (size_t)(m0 + r) * KDIM + kb + cc * 8);
                cp16(st + OFF_B + off, Bp + (size_t)(n0 + r) * KDIM + kb + cc * 8);
            }
            CP_COMMIT();
        };

        GEMM_MAINLOOP(load_tile)

#pragma unroll
        for (int mf = 0; mf < 4; mf++) {
            const int row = m0 + warp_m * 64 + mf * 16 + (lane >> 2);
#pragma unroll
            for (int nf = 0; nf < 4; nf++) {
                const int col = n0 + warp_n * 32 + nf * 8 + (lane & 3) * 2;
                const float bb0 = bp[col], bb1 = bp[col + 1];
                float v0 = fmaf(acc[mf][nf][0], INV_ASCALE, bb0);
                float v1 = fmaf(acc[mf][nf][1], INV_ASCALE, bb1);
                float v2 = fmaf(acc[mf][nf][2], INV_ASCALE, bb0);
                float v3 = fmaf(acc[mf][nf][3], INV_ASCALE, bb1);
                float2* p0 = reinterpret_cast<float2*>(Cp + (size_t)row * CH + col);
                float2* p1 = reinterpret_cast<float2*>(Cp + (size_t)(row + 8) * CH + col);
                *p0 = make_float2(v0, v1);
                *p1 = make_float2(v2, v3);
            }
        }
    }
}

// ---------------- fused f32 -> fp16 convert (4 segments) + zero ------------
#define SEG0 (M_ROWS * CH)
#define SEG1 (QKV_N * CH)
#define SEG2 (CH * CH)
#define SEG3 (CH * CH)
#define CONV_TOTAL (SEG0 + SEG1 + SEG2 + SEG3)

__global__ void conv_all_kernel(const float* __restrict__ x,  __half* __restrict__ dx,
                                const float* __restrict__ w0, __half* __restrict__ d0,
                                const float* __restrict__ w1, __half* __restrict__ d1,
                                const float* __restrict__ w2, __half* __restrict__ d2,
                                float* __restrict__ red, int* __restrict__ cnt)
{
    const int gt = blockIdx.x * blockDim.x + threadIdx.x;
    if (gt < 1 + NMT) cnt[gt] = 0;
    if (gt < 3 * BATCH * CH) red[gt] = 0.0f;

    int i = gt * 4;
    const float* src; __half* dst;
    if (i < SEG0)                      { src = x;  dst = dx; }
    else if ((i -= SEG0) < SEG1)       { src = w0; dst = d0; }
    else if ((i -= SEG1) < SEG2)       { src = w1; dst = d1; }
    else if ((i -= SEG2) < SEG3)       { src = w2; dst = d2; }
    else return;

    float4 v = *reinterpret_cast<const float4*>(src + i);
    __half2* D = reinterpret_cast<__half2*>(dst + i);
    D[0] = __halves2half2(__float2half(v.x), __float2half(v.y));
    D[1] = __halves2half2(__float2half(v.z), __float2half(v.w));
}

// ---------------- launch ----------------
extern "C" void kernel_launch(void* const* d_in, const int* in_sizes, int n_in,
                              void* d_out, int out_size)
{
    const float* x       = (const float*)d_in[0];
    const float* y       = (const float*)d_in[1];
    const float* qkv_w   = (const float*)d_in[2];
    const float* proj1_w = (const float*)d_in[3];
    const float* proj1_b = (const float*)d_in[4];
    const float* proj2_w = (const float*)d_in[5];
    const float* proj2_b = (const float*)d_in[6];
    float* out = (float*)d_out;

    float* red_p;
    int* cnt_p;
    __half *x16, *wq, *w1, *w2, *aL, *aG;
    cudaGetSymbolAddress((void**)&red_p, g_red);
    cudaGetSymbolAddress((void**)&cnt_p, g_cnt);
    cudaGetSymbolAddress((void**)&x16, g_x16);
    cudaGetSymbolAddress((void**)&wq, g_wq);
    cudaGetSymbolAddress((void**)&w1, g_w1);   cudaGetSymbolAddress((void**)&w2, g_w2);
    cudaGetSymbolAddress((void**)&aL, g_aL);   cudaGetSymbolAddress((void**)&aG, g_aG);

    cudaFuncSetAttribute(gemm_fused,
                         cudaFuncAttributeMaxDynamicSharedMemorySize, GEMM_SMEM);

    // 0) one conversion kernel: x + 3 weights -> fp16, zero red + counters
    conv_all_kernel<<<(CONV_TOTAL / 4 + 255) / 256, 256>>>(
        x, x16, qkv_w, wq, proj1_w, w1, proj2_w, w2, red_p, cnt_p);

    // 1) mega-kernel: kv+red (z<12) -> q+attn (z 12..17) -> projections (z 18..29)
    {
        dim3 grid(NMT, 1, 30);
        gemm_fused<<<grid, 256, GEMM_SMEM>>>(
            x16, wq, y, red_p, cnt_p, aL, aG,
            w1, w2, proj1_b, proj2_b, out);
    }
}

// round 17
// speedup vs baseline: 1.3882x; 1.3882x over previous
#include <cuda_runtime.h>
#include <cuda_fp16.h>
#include <cstdint>
#include <math.h>

// ---------------- problem constants ----------------
#define BATCH 4
#define SEQ   4096
#define CH    768
#define NHEAD 12
#define HDIM  64
#define M_ROWS (BATCH * SEQ)          // 16384
#define QKV_N  (3 * CH)               // 2304
#define BNC   (M_ROWS * CH)
#define SCALE 0.125f
#define EPSV  1e-10f
#define KDIM  768
#define ASCALE 4096.0f
#define INV_ASCALE (1.0f / 4096.0f)
#define KV_CTAS 1536                  // 12 * 128
#define NMT 128                       // number of m tiles

// ---------------- scratch (device globals) ----------------
__device__ __half g_x16[M_ROWS * CH];
__device__ __half g_wq[QKV_N * CH];
__device__ __half g_w1[CH * CH], g_w2[CH * CH];
__device__ __half g_aL[M_ROWS * CH];
__device__ __half g_aG[M_ROWS * CH];
__device__ float g_red[3 * BATCH * CH];       // [kv | lkv | ksum]
__device__ int   g_cnt[1 + NMT];              // [0]=kv count, [1+mt]=q count

// ---------------- helpers ----------------
__device__ __forceinline__ float delu_f(float x) {
    return (x >= 0.0f) ? fmaf(10.0f, x, 1.0f) : __expf(10.0f * x);
}

__device__ __forceinline__ uint32_t smem_u32(const void* p) {
    uint32_t a;
    asm("{ .reg .u64 t; cvta.to.shared.u64 t, %1; cvt.u32.u64 %0, t; }" : "=r"(a) : "l"(p));
    return a;
}

__device__ __forceinline__ void cp16(uint32_t s, const void* g) {
    asm volatile("cp.async.cg.shared.global [%0], [%1], 16;" :: "r"(s), "l"(g));
}
#define CP_COMMIT() asm volatile("cp.async.commit_group;" ::: "memory")

__device__ __forceinline__ void ldsm4(uint32_t* r, uint32_t a) {
    asm volatile("ldmatrix.sync.aligned.m8n8.x4.shared.b16 {%0,%1,%2,%3}, [%4];"
                 : "=r"(r[0]), "=r"(r[1]), "=r"(r[2]), "=r"(r[3]) : "r"(a));
}

__device__ __forceinline__ void mma16816(float* c, const uint32_t* a, const uint32_t* b) {
    asm volatile(
        "mma.sync.aligned.m16n8k16.row.col.f32.f16.f16.f32 "
        "{%0,%1,%2,%3},{%4,%5,%6,%7},{%8,%9},{%0,%1,%2,%3};"
        : "+f"(c[0]), "+f"(c[1]), "+f"(c[2]), "+f"(c[3])
        : "r"(a[0]), "r"(a[1]), "r"(a[2]), "r"(a[3]), "r"(b[0]), "r"(b[1]));
}

// ---------------- tiling: CTA 128x128, warp 64x32, BK=64 ----------------
#define BMt 128
#define BNt 128
#define BKt 64
#define NKT (KDIM / BKt)             // 12
#define TILE_B 16384
#define OFF_B TILE_B
#define STG (2 * TILE_B)             // 32 KB per stage
#define NSTG 3
#define GEMM_SMEM (NSTG * STG + 1024)

// R13 mainloop (proven): in-loop swizzle computation.
#define GEMM_MAINLOOP(LOADFN)                                                 \
    LOADFN(0, 0);                                                             \
    LOADFN(1, 1);                                                             \
    const uint32_t arow = (uint32_t)((warp_m * 64 + (lane & 15)) * 128 + (lane >> 4) * 16); \
    const uint32_t brow = (uint32_t)((warp_n * 32 + (lane & 15)) * 128 + (lane >> 4) * 16); \
    for (int c = 0; c < NKT; c++) {                                           \
        const int s = c % NSTG;                                               \
        if (c == NKT - 1) asm volatile("cp.async.wait_group 0;" ::: "memory");\
        else              asm volatile("cp.async.wait_group 1;" ::: "memory");\
        __syncthreads();                                                      \
        if (c + 2 < NKT) LOADFN(c + 2, (c + 2) % NSTG);                       \
        const uint32_t st = sbase + s * STG;                                  \
        _Pragma("unroll")                                                     \
        for (int ks = 0; ks < 4; ks++) {                                      \
            const uint32_t kofs = ks * 32;                                    \
            uint32_t ah[4][4], bh[4][2];                                      \
            _Pragma("unroll")                                                 \
            for (int mf = 0; mf < 4; mf++) {                                  \
                uint32_t off = arow + mf * 2048 + kofs;                       \
                off ^= (off >> 3) & 0x70;                                     \
                ldsm4(ah[mf], st + off);                                      \
            }                                                                 \
            _Pragma("unroll")                                                 \
            for (int gg = 0; gg < 2; gg++) {                                  \
                uint32_t off = brow + gg * 2048 + kofs;                       \
                off ^= (off >> 3) & 0x70;                                     \
                uint32_t qq[4];                                               \
                ldsm4(qq, st + OFF_B + off);                                  \
                bh[gg * 2][0] = qq[0]; bh[gg * 2][1] = qq[2];                 \
                bh[gg * 2 + 1][0] = qq[1]; bh[gg * 2 + 1][1] = qq[3];         \
            }                                                                 \
            _Pragma("unroll")                                                 \
            for (int mf = 0; mf < 4; mf++)                                    \
                _Pragma("unroll")                                             \
                for (int nf = 0; nf < 4; nf++)                                \
                    mma16816(acc[mf][nf], ah[mf], bh[nf]);                    \
        }                                                                     \
    }

// ======== mega-kernel: z<12 kv+red | z in [12,18) q+attn | z>=18 proj ======
__global__ void __launch_bounds__(256, 2)
gemm_fused(const __half* __restrict__ A, const __half* __restrict__ Wq,
           const float* __restrict__ y, float* __restrict__ red,
           int* __restrict__ cnt,
           __half* __restrict__ oL, __half* __restrict__ oG,
           const __half* __restrict__ w1, const __half* __restrict__ w2,
           const float* __restrict__ b1, const float* __restrict__ b2,
           float* __restrict__ out)
{
    extern __shared__ char smraw[];
    const uint32_t sbase = (smem_u32(smraw) + 1023u) & ~1023u;
    const int tid = threadIdx.x;
    const int lane = tid & 31, wid = tid >> 5;
    const int warp_m = wid >> 2, warp_n = wid & 3;
    const int mt = blockIdx.x;
    const int m0 = mt * BMt;
    const int b = m0 >> 12;
    const int z = blockIdx.z;

    float acc[4][4][4];
#pragma unroll
    for (int i = 0; i < 4; i++)
#pragma unroll
        for (int j = 0; j < 4; j++)
#pragma unroll
            for (int e = 0; e < 4; e++) acc[i][j][e] = 0.0f;

    if (z < 12) {
        // ================= kv + diagonal reductions =================
        const int g64 = z * 64;
        auto load_tile = [&](int kt, int s) {
            const uint32_t st = sbase + s * STG;
            const int kb = kt * BKt;
#pragma unroll
            for (int i = tid; i < 1024; i += 256) {
                const int r = i >> 3, cc = i & 7;
                uint32_t off = (uint32_t)(r * 128 + cc * 16);
                off ^= (off >> 3) & 0x70;
                cp16(st + off, A + (size_t)(m0 + r) * KDIM + kb + cc * 8);
                const int rg = (r < 64) ? (CH + g64 + r) : (2 * CH + g64 + r - 64);
                cp16(st + OFF_B + off, Wq + (size_t)rg * KDIM + kb + cc * 8);
            }
            CP_COMMIT();
        };

        GEMM_MAINLOOP(load_tile)

        __syncthreads();
        float* vbuf = reinterpret_cast<float*>(smraw); // [128][65]
        const bool is_v = (warp_n >= 2);

        if (is_v) {
#pragma unroll
            for (int mf = 0; mf < 4; mf++) {
                const int r = warp_m * 64 + mf * 16 + (lane >> 2);
#pragma unroll
                for (int nf = 0; nf < 4; nf++) {
                    const int cl = (warp_n - 2) * 32 + nf * 8 + (lane & 3) * 2;
                    vbuf[r * 65 + cl]           = acc[mf][nf][0];
                    vbuf[r * 65 + cl + 1]       = acc[mf][nf][1];
                    vbuf[(r + 8) * 65 + cl]     = acc[mf][nf][2];
                    vbuf[(r + 8) * 65 + cl + 1] = acc[mf][nf][3];
                }
            }
        }
        __syncthreads();

        if (is_v) {
            float s0[4], s1[4];
#pragma unroll
            for (int nf = 0; nf < 4; nf++) { s0[nf] = 0.f; s1[nf] = 0.f; }
#pragma unroll
            for (int mf = 0; mf < 4; mf++) {
                const int r = m0 + warp_m * 64 + mf * 16 + (lane >> 2);
#pragma unroll
                for (int nf = 0; nf < 4; nf++) {
                    const int cg = g64 + (warp_n - 2) * 32 + nf * 8 + (lane & 3) * 2;
                    const float2 ya = *reinterpret_cast<const float2*>(y + (size_t)r * CH + cg);
                    const float2 yb = *reinterpret_cast<const float2*>(y + (size_t)(r + 8) * CH + cg);
                    s0[nf] = fmaf(delu_f(ya.x), acc[mf][nf][0], s0[nf]);
                    s1[nf] = fmaf(delu_f(ya.y), acc[mf][nf][1], s1[nf]);
                    s0[nf] = fmaf(delu_f(yb.x), acc[mf][nf][2], s0[nf]);
                    s1[nf] = fmaf(delu_f(yb.y), acc[mf][nf][3], s1[nf]);
                }
            }
#pragma unroll
            for (int nf = 0; nf < 4; nf++) {
#pragma unroll
                for (int off = 4; off <= 16; off <<= 1) {
                    s0[nf] += __shfl_xor_sync(0xffffffffu, s0[nf], off);
                    s1[nf] += __shfl_xor_sync(0xffffffffu, s1[nf], off);
                }
            }
            if (lane < 4) {
#pragma unroll
                for (int nf = 0; nf < 4; nf++) {
                    const int cg = g64 + (warp_n - 2) * 32 + nf * 8 + lane * 2;
                    atomicAdd(&red[BATCH * CH + b * CH + cg],     s0[nf]);
                    atomicAdd(&red[BATCH * CH + b * CH + cg + 1], s1[nf]);
                }
            }
        } else {
            float p0[4], p1[4], k0[4], k1[4];
#pragma unroll
            for (int nf = 0; nf < 4; nf++) { p0[nf] = p1[nf] = k0[nf] = k1[nf] = 0.f; }
#pragma unroll
            for (int mf = 0; mf < 4; mf++) {
                const int r = warp_m * 64 + mf * 16 + (lane >> 2);
#pragma unroll
                for (int nf = 0; nf < 4; nf++) {
                    const int cl = warp_n * 32 + nf * 8 + (lane & 3) * 2;
                    const float ka = delu_f(acc[mf][nf][0]);
                    const float kb = delu_f(acc[mf][nf][1]);
                    const float kc = delu_f(acc[mf][nf][2]);
                    const float kd = delu_f(acc[mf][nf][3]);
                    p0[nf] = fmaf(ka, vbuf[r * 65 + cl],           p0[nf]);
                    p1[nf] = fmaf(kb, vbuf[r * 65 + cl + 1],       p1[nf]);
                    p0[nf] = fmaf(kc, vbuf[(r + 8) * 65 + cl],     p0[nf]);
                    p1[nf] = fmaf(kd, vbuf[(r + 8) * 65 + cl + 1], p1[nf]);
                    k0[nf] += ka + kc;
                    k1[nf] += kb + kd;
                }
            }
#pragma unroll
            for (int nf = 0; nf < 4; nf++) {
#pragma unroll
                for (int off = 4; off <= 16; off <<= 1) {
                    p0[nf] += __shfl_xor_sync(0xffffffffu, p0[nf], off);
                    p1[nf] += __shfl_xor_sync(0xffffffffu, p1[nf], off);
                    k0[nf] += __shfl_xor_sync(0xffffffffu, k0[nf], off);
                    k1[nf] += __shfl_xor_sync(0xffffffffu, k1[nf], off);
                }
            }
            if (lane < 4) {
#pragma unroll
                for (int nf = 0; nf < 4; nf++) {
                    const int cg = g64 + warp_n * 32 + nf * 8 + lane * 2;
                    atomicAdd(&red[b * CH + cg],     p0[nf]);
                    atomicAdd(&red[b * CH + cg + 1], p1[nf]);
                    atomicAdd(&red[2 * BATCH * CH + b * CH + cg],     k0[nf]);
                    atomicAdd(&red[2 * BATCH * CH + b * CH + cg + 1], k1[nf]);
                }
            }
        }
        __syncthreads();
        if (tid == 0) {
            __threadfence();
            atomicAdd(&cnt[0], 1);
        }
    } else if (z < 18) {
        // ================= q GEMM + norm + attention =================
        const int n0 = (z - 12) * BNt;
        auto load_tile = [&](int kt, int s) {
            const uint32_t st = sbase + s * STG;
            const int kb = kt * BKt;
#pragma unroll
            for (int i = tid; i < 1024; i += 256) {
                const int r = i >> 3, cc = i & 7;
                uint32_t off = (uint32_t)(r * 128 + cc * 16);
                off ^= (off >> 3) & 0x70;
                cp16(st + off,         A + (size_t)(m0 + r) * KDIM + kb + cc * 8);
                cp16(st + OFF_B + off, Wq + (size_t)(n0 + r) * KDIM + kb + cc * 8);
            }
            CP_COMMIT();
        };

        GEMM_MAINLOOP(load_tile)

        // acquire: all kv CTAs done
        if (tid == 0) {
            while (*reinterpret_cast<volatile int*>(&cnt[0]) < KV_CTAS) { }
            __threadfence();
        }
        __syncthreads();

        const float* ksb  = red + 2 * BATCH * CH + b * CH;
        const float* kvb  = red + b * CH;
        const float* lkvb = red + BATCH * CH + b * CH;

        float ks0[4], ks1[4], kv0[4], kv1[4], lk0[4], lk1[4];
#pragma unroll
        for (int nf = 0; nf < 4; nf++) {
            const int col = n0 + warp_n * 32 + nf * 8 + (lane & 3) * 2;
            ks0[nf] = ksb[col] + EPSV;       ks1[nf] = ksb[col + 1] + EPSV;
            kv0[nf] = kvb[col] * SCALE;      kv1[nf] = kvb[col + 1] * SCALE;
            lk0[nf] = lkvb[col] * SCALE;     lk1[nf] = lkvb[col + 1] * SCALE;
        }

#pragma unroll
        for (int mf = 0; mf < 4; mf++)
#pragma unroll
            for (int nf = 0; nf < 4; nf++)
#pragma unroll
                for (int e = 0; e < 4; e++) acc[mf][nf][e] = delu_f(acc[mf][nf][e]);

        float (*psum)[128] = reinterpret_cast<float (*)[128]>(smraw); // [4][128]

#pragma unroll
        for (int mf = 0; mf < 4; mf++) {
            float pa = 0.f, pb = 0.f;
#pragma unroll
            for (int nf = 0; nf < 4; nf++) {
                pa += acc[mf][nf][0] * ks0[nf] + acc[mf][nf][1] * ks1[nf];
                pb += acc[mf][nf][2] * ks0[nf] + acc[mf][nf][3] * ks1[nf];
            }
            pa += __shfl_xor_sync(0xffffffffu, pa, 1);
            pa += __shfl_xor_sync(0xffffffffu, pa, 2);
            pb += __shfl_xor_sync(0xffffffffu, pb, 1);
            pb += __shfl_xor_sync(0xffffffffu, pb, 2);
            if ((lane & 3) == 0) {
                const int rl = warp_m * 64 + mf * 16 + (lane >> 2);
                psum[warp_n][rl]     = pa;
                psum[warp_n][rl + 8] = pb;
            }
        }
        __syncthreads();

        const int hw = warp_n & ~1;
#pragma unroll
        for (int mf = 0; mf < 4; mf++) {
            const int rl = warp_m * 64 + mf * 16 + (lane >> 2);
            const float na = ASCALE / (psum[hw][rl]     + psum[hw + 1][rl]);
            const float nb = ASCALE / (psum[hw][rl + 8] + psum[hw + 1][rl + 8]);
            const int row = m0 + rl;
#pragma unroll
            for (int nf = 0; nf < 4; nf++) {
                const int col = n0 + warp_n * 32 + nf * 8 + (lane & 3) * 2;
                const size_t i0 = (size_t)row * CH + col;
                const size_t i1 = (size_t)(row + 8) * CH + col;
                *reinterpret_cast<__half2*>(oL + i0) = __halves2half2(
                    __float2half(acc[mf][nf][0] * kv0[nf] * na),
                    __float2half(acc[mf][nf][1] * kv1[nf] * na));
                *reinterpret_cast<__half2*>(oL + i1) = __halves2half2(
                    __float2half(acc[mf][nf][2] * kv0[nf] * nb),
                    __float2half(acc[mf][nf][3] * kv1[nf] * nb));
                *reinterpret_cast<__half2*>(oG + i0) = __halves2half2(
                    __float2half(acc[mf][nf][0] * lk0[nf] * na),
                    __float2half(acc[mf][nf][1] * lk1[nf] * na));
                *reinterpret_cast<__half2*>(oG + i1) = __halves2half2(
                    __float2half(acc[mf][nf][2] * lk0[nf] * nb),
                    __float2half(acc[mf][nf][3] * lk1[nf] * nb));
            }
        }
        // release this m-tile for projections
        __syncthreads();
        if (tid == 0) {
            __threadfence();
            atomicAdd(&cnt[1 + mt], 1);
        }
    } else {
        // ================= projections (z = 18..29) =================
        const int zz = z - 18;
        const int p  = zz / 6;                 // 0 -> proj1, 1 -> proj2
        const int n0 = (zz % 6) * BNt;
        const __half* Ap = p ? oG : oL;
        const __half* Bp = p ? w2 : w1;
        const float* bp  = p ? b2 : b1;
        float* Cp        = out + (size_t)p * BNC;

        // acquire: all 6 q CTAs for this m-tile finished
        if (tid == 0) {
            while (*reinterpret_cast<volatile int*>(&cnt[1 + mt]) < 6) { }
            __threadfence();
        }
        __syncthreads();

        auto load_tile = [&](int kt, int s) {
            const uint32_t st = sbase + s * STG;
            const int kb = kt * BKt;
#pragma unroll
            for (int i = tid; i < 1024; i += 256) {
                const int r = i >> 3, cc = i & 7;
                uint32_t off = (uint32_t)(r * 128 + cc * 16);
                off ^= (off >> 3) & 0x70;
                cp16(st + off,         Ap + (size_t)(m0 + r) * KDIM + kb + cc * 8);
                cp16(st + OFF_B + off, Bp + (size_t)(n0 + r) * KDIM + kb + cc * 8);
            }
            CP_COMMIT();
        };

        GEMM_MAINLOOP(load_tile)

#pragma unroll
        for (int mf = 0; mf < 4; mf++) {
            const int row = m0 + warp_m * 64 + mf * 16 + (lane >> 2);
#pragma unroll
            for (int nf = 0; nf < 4; nf++) {
                const int col = n0 + warp_n * 32 + nf * 8 + (lane & 3) * 2;
                const float bb0 = bp[col], bb1 = bp[col + 1];
                float v0 = fmaf(acc[mf][nf][0], INV_ASCALE, bb0);
                float v1 = fmaf(acc[mf][nf][1], INV_ASCALE, bb1);
                float v2 = fmaf(acc[mf][nf][2], INV_ASCALE, bb0);
                float v3 = fmaf(acc[mf][nf][3], INV_ASCALE, bb1);
                float2* p0 = reinterpret_cast<float2*>(Cp + (size_t)row * CH + col);
                float2* p1 = reinterpret_cast<float2*>(Cp + (size_t)(row + 8) * CH + col);
                *p0 = make_float2(v0, v1);
                *p1 = make_float2(v2, v3);
            }
        }
    }
}

// ---------------- fused f32 -> fp16 convert (4 segments) + zero ------------
// 4 independent float4s per thread (MLP=4); segment sizes are multiples of
// 16 floats so a thread's 16-float range never crosses a segment boundary.
#define SEG0 (M_ROWS * CH)
#define SEG1 (QKV_N * CH)
#define SEG2 (CH * CH)
#define SEG3 (CH * CH)
#define CONV_TOTAL (SEG0 + SEG1 + SEG2 + SEG3)

__global__ void conv_all_kernel(const float* __restrict__ x,  __half* __restrict__ dx,
                                const float* __restrict__ w0, __half* __restrict__ d0,
                                const float* __restrict__ w1, __half* __restrict__ d1,
                                const float* __restrict__ w2, __half* __restrict__ d2,
                                float* __restrict__ red, int* __restrict__ cnt)
{
    const int gt = blockIdx.x * blockDim.x + threadIdx.x;
    if (gt < 1 + NMT) cnt[gt] = 0;
    if (gt < 3 * BATCH * CH) red[gt] = 0.0f;

    int i = gt * 16;
    if (i >= CONV_TOTAL) return;
    const float* src; __half* dst;
    if (i < SEG0)                      { src = x;  dst = dx; }
    else if ((i -= SEG0) < SEG1)       { src = w0; dst = d0; }
    else if ((i -= SEG1) < SEG2)       { src = w1; dst = d1; }
    else                               { i -= SEG2; src = w2; dst = d2; }

    const float4* S = reinterpret_cast<const float4*>(src + i);
    __half2* D = reinterpret_cast<__half2*>(dst + i);
    float4 v0 = S[0], v1 = S[1], v2 = S[2], v3 = S[3];
    D[0] = __halves2half2(__float2half(v0.x), __float2half(v0.y));
    D[1] = __halves2half2(__float2half(v0.z), __float2half(v0.w));
    D[2] = __halves2half2(__float2half(v1.x), __float2half(v1.y));
    D[3] = __halves2half2(__float2half(v1.z), __float2half(v1.w));
    D[4] = __halves2half2(__float2half(v2.x), __float2half(v2.y));
    D[5] = __halves2half2(__float2half(v2.z), __float2half(v2.w));
    D[6] = __halves2half2(__float2half(v3.x), __float2half(v3.y));
    D[7] = __halves2half2(__float2half(v3.z), __float2half(v3.w));
}

// ---------------- launch ----------------
extern "C" void kernel_launch(void* const* d_in, const int* in_sizes, int n_in,
                              void* d_out, int out_size)
{
    const float* x       = (const float*)d_in[0];
    const float* y       = (const float*)d_in[1];
    const float* qkv_w   = (const float*)d_in[2];
    const float* proj1_w = (const float*)d_in[3];
    const float* proj1_b = (const float*)d_in[4];
    const float* proj2_w = (const float*)d_in[5];
    const float* proj2_b = (const float*)d_in[6];
    float* out = (float*)d_out;

    float* red_p;
    int* cnt_p;
    __half *x16, *wq, *w1, *w2, *aL, *aG;
    cudaGetSymbolAddress((void**)&red_p, g_red);
    cudaGetSymbolAddress((void**)&cnt_p, g_cnt);
    cudaGetSymbolAddress((void**)&x16, g_x16);
    cudaGetSymbolAddress((void**)&wq, g_wq);
    cudaGetSymbolAddress((void**)&w1, g_w1);   cudaGetSymbolAddress((void**)&w2, g_w2);
    cudaGetSymbolAddress((void**)&aL, g_aL);   cudaGetSymbolAddress((void**)&aG, g_aG);

    cudaFuncSetAttribute(gemm_fused,
                         cudaFuncAttributeMaxDynamicSharedMemorySize, GEMM_SMEM);

    // 0) one conversion kernel: x + 3 weights -> fp16, zero red + counters
    conv_all_kernel<<<(CONV_TOTAL / 16 + 255) / 256, 256>>>(
        x, x16, qkv_w, wq, proj1_w, w1, proj2_w, w2, red_p, cnt_p);

    // 1) mega-kernel: kv+red (z<12) -> q+attn (z 12..17) -> projections (z 18..29)
    {
        dim3 grid(NMT, 1, 30);
        gemm_fused<<<grid, 256, GEMM_SMEM>>>(
            x16, wq, y, red_p, cnt_p, aL, aG,
            w1, w2, proj1_b, proj2_b, out);
    }
}